// round 1
// baseline (speedup 1.0000x reference)
#include <cuda_runtime.h>

// Problem constants (from reference)
#define NX_MAX 100000
#define NC_MAX 50000
#define NR_MAX 1000
#define HID 64

// Scratch (allocation-free rule: __device__ globals)
__device__ float g_agg[(size_t)NX_MAX * HID];
__device__ float g_txx[(size_t)NX_MAX * HID];
__device__ float g_tcx[(size_t)NC_MAX * HID];
__device__ float g_trx[(size_t)NR_MAX * HID];

// Y[row][j] = (relu?)( sum_k X[row][k] * W[j][k] + B[j] ), j in [0,64)
// One thread per row, 64 fp32 accumulators, W transposed in shared (broadcast reads).
template <int F, bool RELU>
__global__ void __launch_bounds__(128) gemm64_kernel(
    const float* __restrict__ X, int N,
    const float* __restrict__ W,   // [64][F] row-major
    const float* __restrict__ B,   // [64]
    float* __restrict__ Y)         // [N][64]
{
    __shared__ float Wt[F * 64];   // Wt[k*64 + j] = W[j][k]
    __shared__ float Bs[64];

    const int tid = threadIdx.x;
    for (int i = tid; i < F * 64; i += 128) {
        int j = i / F;
        int k = i - j * F;
        Wt[k * 64 + j] = W[i];
    }
    if (tid < 64) Bs[tid] = B[tid];
    __syncthreads();

    const int row = blockIdx.x * 128 + tid;
    if (row >= N) return;

    float4 acc[16];
    const float4* Bs4 = reinterpret_cast<const float4*>(Bs);
#pragma unroll
    for (int j = 0; j < 16; j++) acc[j] = Bs4[j];

    const float4* X4  = reinterpret_cast<const float4*>(X + (size_t)row * F);
    const float4* Wt4 = reinterpret_cast<const float4*>(Wt);

#pragma unroll 2
    for (int k4 = 0; k4 < F / 4; k4++) {
        const float4 xv = X4[k4];
#pragma unroll
        for (int kk = 0; kk < 4; kk++) {
            const float xs = (kk == 0) ? xv.x : (kk == 1) ? xv.y : (kk == 2) ? xv.z : xv.w;
            const float4* wrow = Wt4 + (size_t)(k4 * 4 + kk) * 16;
#pragma unroll
            for (int j = 0; j < 16; j++) {
                float4 w = wrow[j];   // broadcast across warp
                acc[j].x += xs * w.x;
                acc[j].y += xs * w.y;
                acc[j].z += xs * w.z;
                acc[j].w += xs * w.w;
            }
        }
    }

    float4* Y4 = reinterpret_cast<float4*>(Y + (size_t)row * 64);
#pragma unroll
    for (int j = 0; j < 16; j++) {
        float4 v = acc[j];
        if (RELU) {
            v.x = fmaxf(v.x, 0.0f);
            v.y = fmaxf(v.y, 0.0f);
            v.z = fmaxf(v.z, 0.0f);
            v.w = fmaxf(v.w, 0.0f);
        }
        Y4[j] = v;
    }
}

// agg[dst] += T[src] over edges, 16 threads (one float4 lane each) per edge.
__global__ void scatter_kernel(const int* __restrict__ src, const int* __restrict__ dst,
                               int E, const float4* __restrict__ T,
                               float4* __restrict__ agg)
{
    const int gid = blockIdx.x * blockDim.x + threadIdx.x;
    if (gid >= E * 16) return;
    const int e = gid >> 4;
    const int l = gid & 15;
    const int s = src[e];
    const int d = dst[e];
    const float4 v = T[(size_t)s * 16 + l];
    float4* p = agg + (size_t)d * 16 + l;
    asm volatile("red.global.add.v4.f32 [%0], {%1, %2, %3, %4};"
                 :: "l"(p), "f"(v.x), "f"(v.y), "f"(v.z), "f"(v.w)
                 : "memory");
}

extern "C" void kernel_launch(void* const* d_in, const int* in_sizes, int n_in,
                              void* d_out, int out_size)
{
    const float* x      = (const float*)d_in[0];
    const float* c      = (const float*)d_in[1];
    const float* r      = (const float*)d_in[2];
    const int*   e_xx_s = (const int*)d_in[3];
    const int*   e_xx_d = (const int*)d_in[4];
    const int*   e_cx_s = (const int*)d_in[5];
    const int*   e_cx_d = (const int*)d_in[6];
    const int*   e_rx_s = (const int*)d_in[7];
    const int*   e_rx_d = (const int*)d_in[8];
    const float* W_x    = (const float*)d_in[9];
    const float* b_x    = (const float*)d_in[10];
    const float* W_c    = (const float*)d_in[11];
    const float* b_c    = (const float*)d_in[12];
    const float* W_r    = (const float*)d_in[13];
    const float* b_r    = (const float*)d_in[14];
    const float* W_xx   = (const float*)d_in[15];
    const float* b_xx   = (const float*)d_in[16];
    const float* W_cx   = (const float*)d_in[17];
    const float* b_cx   = (const float*)d_in[18];
    const float* W_rx   = (const float*)d_in[19];
    const float* b_rx   = (const float*)d_in[20];
    const float* W_pool = (const float*)d_in[21];
    const float* b_pool = (const float*)d_in[22];

    const int nx  = in_sizes[0] / 64;
    const int nc  = in_sizes[1] / 32;
    const int nr  = in_sizes[2] / 48;
    const int Exx = in_sizes[3];
    const int Ecx = in_sizes[5];
    const int Erx = in_sizes[7];

    float *agg, *txx, *tcx, *trx;
    cudaGetSymbolAddress((void**)&agg, g_agg);
    cudaGetSymbolAddress((void**)&txx, g_txx);
    cudaGetSymbolAddress((void**)&tcx, g_tcx);
    cudaGetSymbolAddress((void**)&trx, g_trx);

    float* out   = (float*)d_out;
    float* x_out = out;
    float* c_out = out + (size_t)nx * 64;
    float* r_out = out + (size_t)nx * 64 + (size_t)nc * 64;

    // Per-node transforms (self-loop term initializes agg)
    gemm64_kernel<64, true ><<<(nx + 127) / 128, 128>>>(x, nx, W_x,  b_x,  agg);
    gemm64_kernel<64, true ><<<(nx + 127) / 128, 128>>>(x, nx, W_xx, b_xx, txx);
    gemm64_kernel<32, true ><<<(nc + 127) / 128, 128>>>(c, nc, W_cx, b_cx, tcx);
    gemm64_kernel<32, true ><<<(nc + 127) / 128, 128>>>(c, nc, W_c,  b_c,  c_out);
    gemm64_kernel<48, true ><<<(nr + 127) / 128, 128>>>(r, nr, W_rx, b_rx, trx);
    gemm64_kernel<48, true ><<<(nr + 127) / 128, 128>>>(r, nr, W_r,  b_r,  r_out);

    // Edge scatter-adds into agg
    scatter_kernel<<<((long long)Exx * 16 + 255) / 256, 256>>>(e_xx_s, e_xx_d, Exx,
                                                               (const float4*)txx, (float4*)agg);
    scatter_kernel<<<((long long)Ecx * 16 + 255) / 256, 256>>>(e_cx_s, e_cx_d, Ecx,
                                                               (const float4*)tcx, (float4*)agg);
    scatter_kernel<<<((long long)Erx * 16 + 255) / 256, 256>>>(e_rx_s, e_rx_d, Erx,
                                                               (const float4*)trx, (float4*)agg);

    // Output projection (no relu)
    gemm64_kernel<64, false><<<(nx + 127) / 128, 128>>>(agg, nx, W_pool, b_pool, x_out);
}

// round 2
// speedup vs baseline: 1.0033x; 1.0033x over previous
#include <cuda_runtime.h>

// Problem constants (from reference)
#define NX_MAX 100000
#define NC_MAX 50000
#define NR_MAX 1000
#define HID 64

// Scratch (allocation-free rule: __device__ globals)
__device__ float g_agg[(size_t)NX_MAX * HID];
__device__ float g_txx[(size_t)NX_MAX * HID];
__device__ float g_tcx[(size_t)NC_MAX * HID];
__device__ float g_trx[(size_t)NR_MAX * HID];

// ---------- packed f32x2 helpers (sm_103a FFMA2) ----------
__device__ __forceinline__ unsigned long long pack2(float x) {
    unsigned long long r;
    asm("mov.b64 %0, {%1, %1};" : "=l"(r) : "f"(x));
    return r;
}
__device__ __forceinline__ unsigned long long fma2(unsigned long long a,
                                                   unsigned long long b,
                                                   unsigned long long c) {
    unsigned long long d;
    asm("fma.rn.f32x2 %0, %1, %2, %3;" : "=l"(d) : "l"(a), "l"(b), "l"(c));
    return d;
}
__device__ __forceinline__ void unpack2(unsigned long long v, float& lo, float& hi) {
    asm("mov.b64 {%0, %1}, %2;" : "=f"(lo), "=f"(hi) : "l"(v));
}

// ---------------------------------------------------------------------------
// gemm_v2: Y[row][0:64] = (relu?)(X[row][0:F] @ W^T + B), one thread per row,
// 128 rows per CTA. X staged in smem (coalesced load, group-swizzled rows),
// FFMA2 packed math, output transposed through smem for coalesced stores.
// F must be a multiple of 4 and power-of-2-friendly for the swizzle (32/64).
// ---------------------------------------------------------------------------
template <int F, bool RELU>
__global__ void __launch_bounds__(128, 4) gemm_v2(
    const float* __restrict__ X, int N,
    const float* __restrict__ W,   // [64][F] row-major
    const float* __restrict__ B,   // [64]
    float* __restrict__ Y)         // [N][64]
{
    constexpr int NG  = F / 4;                         // float4 groups per row
    constexpr int XSZ = (128 * F > 8192) ? 128 * F : 8192;  // floats (epilogue needs 128*64)
    __shared__ float Xbuf[XSZ];
    __shared__ float Wt[F * 64];                       // Wt[k*64 + j] = W[j][k]

    const int tid = threadIdx.x;
    const int rowBase = blockIdx.x * 128;

    // ---- stage W transposed (broadcast-friendly) ----
    for (int i = tid; i < F * 64; i += 128) {
        int j = i / F;
        int k = i - j * F;
        Wt[k * 64 + j] = W[i];
    }

    // ---- stage X tile coalesced, group-swizzled per row ----
    {
        float4* Xb4 = reinterpret_cast<float4*>(Xbuf);
        const float4* X4 = reinterpret_cast<const float4*>(X);
        for (int i = tid; i < 128 * NG; i += 128) {
            int r = i / NG;
            int g = i - r * NG;
            float4 v = make_float4(0.f, 0.f, 0.f, 0.f);
            int row = rowBase + r;
            if (row < N) v = X4[(size_t)row * NG + g];
            Xb4[r * NG + ((g + r) & (NG - 1))] = v;
        }
    }
    __syncthreads();

    // ---- accumulators: 64 outputs as 32 packed f32x2, init with bias ----
    unsigned long long acc[32];
    {
        const unsigned long long* B2 = reinterpret_cast<const unsigned long long*>(B);
#pragma unroll
        for (int j = 0; j < 32; j++) acc[j] = B2[j];   // uniform LDG
    }

    // ---- main loop over K ----
    {
        const float4* Xb4 = reinterpret_cast<const float4*>(Xbuf);
#pragma unroll 2
        for (int kg = 0; kg < NG; kg++) {
            float4 xv = Xb4[tid * NG + ((kg + tid) & (NG - 1))];
#pragma unroll
            for (int ko = 0; ko < 4; ko++) {
                float xs = (ko == 0) ? xv.x : (ko == 1) ? xv.y : (ko == 2) ? xv.z : xv.w;
                unsigned long long x2 = pack2(xs);
                const ulonglong2* wrow =
                    reinterpret_cast<const ulonglong2*>(&Wt[(kg * 4 + ko) * 64]);
#pragma unroll
                for (int j = 0; j < 16; j++) {
                    ulonglong2 w = wrow[j];            // LDS.128 broadcast
                    acc[2 * j]     = fma2(x2, w.x, acc[2 * j]);
                    acc[2 * j + 1] = fma2(x2, w.y, acc[2 * j + 1]);
                }
            }
        }
    }

    // ---- epilogue: transpose through smem for coalesced stores ----
    __syncthreads();   // Xbuf/Wt reads done; reuse Xbuf as output staging
    {
        float4* Ob4 = reinterpret_cast<float4*>(Xbuf);
#pragma unroll
        for (int j = 0; j < 16; j++) {
            float4 v;
            unpack2(acc[2 * j],     v.x, v.y);
            unpack2(acc[2 * j + 1], v.z, v.w);
            if (RELU) {
                v.x = fmaxf(v.x, 0.f); v.y = fmaxf(v.y, 0.f);
                v.z = fmaxf(v.z, 0.f); v.w = fmaxf(v.w, 0.f);
            }
            Ob4[tid * 16 + ((j + tid) & 15)] = v;
        }
        __syncthreads();
        float4* Y4 = reinterpret_cast<float4*>(Y);
        for (int i = tid; i < 128 * 16; i += 128) {
            int r = i >> 4;
            int g = i & 15;
            int row = rowBase + r;
            if (row < N)
                Y4[(size_t)row * 16 + g] = Ob4[r * 16 + ((g + r) & 15)];
        }
    }
}

// ---------------------------------------------------------------------------
// Small-N fallback GEMM (F=48, N=1000): v1-style, negligible cost.
// ---------------------------------------------------------------------------
template <int F, bool RELU>
__global__ void __launch_bounds__(128) gemm_small(
    const float* __restrict__ X, int N,
    const float* __restrict__ W, const float* __restrict__ B,
    float* __restrict__ Y)
{
    __shared__ float Wt[F * 64];
    __shared__ float Bs[64];
    const int tid = threadIdx.x;
    for (int i = tid; i < F * 64; i += 128) {
        int j = i / F;
        int k = i - j * F;
        Wt[k * 64 + j] = W[i];
    }
    if (tid < 64) Bs[tid] = B[tid];
    __syncthreads();

    const int row = blockIdx.x * 128 + tid;
    if (row >= N) return;

    float4 acc[16];
    const float4* Bs4 = reinterpret_cast<const float4*>(Bs);
#pragma unroll
    for (int j = 0; j < 16; j++) acc[j] = Bs4[j];

    const float4* X4  = reinterpret_cast<const float4*>(X + (size_t)row * F);
    const float4* Wt4 = reinterpret_cast<const float4*>(Wt);
#pragma unroll 2
    for (int k4 = 0; k4 < F / 4; k4++) {
        const float4 xv = X4[k4];
#pragma unroll
        for (int kk = 0; kk < 4; kk++) {
            const float xs = (kk == 0) ? xv.x : (kk == 1) ? xv.y : (kk == 2) ? xv.z : xv.w;
            const float4* wrow = Wt4 + (size_t)(k4 * 4 + kk) * 16;
#pragma unroll
            for (int j = 0; j < 16; j++) {
                float4 w = wrow[j];
                acc[j].x += xs * w.x;
                acc[j].y += xs * w.y;
                acc[j].z += xs * w.z;
                acc[j].w += xs * w.w;
            }
        }
    }
    float4* Y4 = reinterpret_cast<float4*>(Y + (size_t)row * 64);
#pragma unroll
    for (int j = 0; j < 16; j++) {
        float4 v = acc[j];
        if (RELU) {
            v.x = fmaxf(v.x, 0.f); v.y = fmaxf(v.y, 0.f);
            v.z = fmaxf(v.z, 0.f); v.w = fmaxf(v.w, 0.f);
        }
        Y4[j] = v;
    }
}

// agg[dst] += T[src] over edges, 16 threads (one float4 lane each) per edge.
__global__ void scatter_kernel(const int* __restrict__ src, const int* __restrict__ dst,
                               int E, const float4* __restrict__ T,
                               float4* __restrict__ agg)
{
    const int gid = blockIdx.x * blockDim.x + threadIdx.x;
    if (gid >= E * 16) return;
    const int e = gid >> 4;
    const int l = gid & 15;
    const int s = src[e];
    const int d = dst[e];
    const float4 v = T[(size_t)s * 16 + l];
    float4* p = agg + (size_t)d * 16 + l;
    asm volatile("red.global.add.v4.f32 [%0], {%1, %2, %3, %4};"
                 :: "l"(p), "f"(v.x), "f"(v.y), "f"(v.z), "f"(v.w)
                 : "memory");
}

extern "C" void kernel_launch(void* const* d_in, const int* in_sizes, int n_in,
                              void* d_out, int out_size)
{
    const float* x      = (const float*)d_in[0];
    const float* c      = (const float*)d_in[1];
    const float* r      = (const float*)d_in[2];
    const int*   e_xx_s = (const int*)d_in[3];
    const int*   e_xx_d = (const int*)d_in[4];
    const int*   e_cx_s = (const int*)d_in[5];
    const int*   e_cx_d = (const int*)d_in[6];
    const int*   e_rx_s = (const int*)d_in[7];
    const int*   e_rx_d = (const int*)d_in[8];
    const float* W_x    = (const float*)d_in[9];
    const float* b_x    = (const float*)d_in[10];
    const float* W_c    = (const float*)d_in[11];
    const float* b_c    = (const float*)d_in[12];
    const float* W_r    = (const float*)d_in[13];
    const float* b_r    = (const float*)d_in[14];
    const float* W_xx   = (const float*)d_in[15];
    const float* b_xx   = (const float*)d_in[16];
    const float* W_cx   = (const float*)d_in[17];
    const float* b_cx   = (const float*)d_in[18];
    const float* W_rx   = (const float*)d_in[19];
    const float* b_rx   = (const float*)d_in[20];
    const float* W_pool = (const float*)d_in[21];
    const float* b_pool = (const float*)d_in[22];

    const int nx  = in_sizes[0] / 64;
    const int nc  = in_sizes[1] / 32;
    const int nr  = in_sizes[2] / 48;
    const int Exx = in_sizes[3];
    const int Ecx = in_sizes[5];
    const int Erx = in_sizes[7];

    float *agg, *txx, *tcx, *trx;
    cudaGetSymbolAddress((void**)&agg, g_agg);
    cudaGetSymbolAddress((void**)&txx, g_txx);
    cudaGetSymbolAddress((void**)&tcx, g_tcx);
    cudaGetSymbolAddress((void**)&trx, g_trx);

    float* out   = (float*)d_out;
    float* x_out = out;
    float* c_out = out + (size_t)nx * 64;
    float* r_out = out + (size_t)nx * 64 + (size_t)nc * 64;

    const int gx = (nx + 127) / 128;
    const int gc = (nc + 127) / 128;
    const int gr = (nr + 127) / 128;

    // Per-node transforms (self-loop term initializes agg)
    gemm_v2<64, true ><<<gx, 128>>>(x, nx, W_x,  b_x,  agg);
    gemm_v2<64, true ><<<gx, 128>>>(x, nx, W_xx, b_xx, txx);
    gemm_v2<32, true ><<<gc, 128>>>(c, nc, W_cx, b_cx, tcx);
    gemm_v2<32, true ><<<gc, 128>>>(c, nc, W_c,  b_c,  c_out);
    gemm_small<48, true ><<<gr, 128>>>(r, nr, W_rx, b_rx, trx);
    gemm_small<48, true ><<<gr, 128>>>(r, nr, W_r,  b_r,  r_out);

    // Edge scatter-adds into agg
    scatter_kernel<<<((long long)Exx * 16 + 255) / 256, 256>>>(e_xx_s, e_xx_d, Exx,
                                                               (const float4*)txx, (float4*)agg);
    scatter_kernel<<<((long long)Ecx * 16 + 255) / 256, 256>>>(e_cx_s, e_cx_d, Ecx,
                                                               (const float4*)tcx, (float4*)agg);
    scatter_kernel<<<((long long)Erx * 16 + 255) / 256, 256>>>(e_rx_s, e_rx_d, Erx,
                                                               (const float4*)trx, (float4*)agg);

    // Output projection (no relu)
    gemm_v2<64, false><<<gx, 128>>>(agg, nx, W_pool, b_pool, x_out);
}

// round 3
// speedup vs baseline: 1.1068x; 1.1032x over previous
#include <cuda_runtime.h>

#define NX_MAX 100000
#define NC_MAX 50000
#define NR_MAX 1000
#define HID 64

__device__ float g_agg[(size_t)NX_MAX * HID];
__device__ float g_txx[(size_t)NX_MAX * HID];
__device__ float g_tcx[(size_t)NC_MAX * HID];
__device__ float g_trx[(size_t)NR_MAX * HID];

// ---------- packed f32x2 helpers (sm_103a FFMA2) ----------
__device__ __forceinline__ unsigned long long pack2(float x) {
    unsigned long long r;
    asm("mov.b64 %0, {%1, %1};" : "=l"(r) : "f"(x));
    return r;
}
__device__ __forceinline__ unsigned long long fma2(unsigned long long a,
                                                   unsigned long long b,
                                                   unsigned long long c) {
    unsigned long long d;
    asm("fma.rn.f32x2 %0, %1, %2, %3;" : "=l"(d) : "l"(a), "l"(b), "l"(c));
    return d;
}
__device__ __forceinline__ void unpack2(unsigned long long v, float& lo, float& hi) {
    asm("mov.b64 {%0, %1}, %2;" : "=f"(lo), "=f"(hi) : "l"(v));
}

// ---------------------------------------------------------------------------
// gemm_v3: Y[128-row tile][64] = (relu?)(X @ W^T + B).
// 128 threads; thread (tr,tc) computes 8 rows x 8 cols via f32x2 over row-pairs.
// Rows of thread: 32*j + 2*tr + {0,1}, j=0..3. Cols: tc*8..tc*8+7.
// Xs: transposed [F][128], swizzled col = row ^ (2*((k>>2)&15))  (LDS.64 pairs).
// WsD: duplicated (w,w) pairs, 8 groups of 16 floats at 20-float stagger,
//      row stride 164 floats -> conflict-free LDS.128.
// ---------------------------------------------------------------------------
template <int F, bool RELU>
__global__ void __launch_bounds__(128, 3) gemm_v3(
    const float* __restrict__ X, int N,
    const float* __restrict__ W,   // [64][F] row-major
    const float* __restrict__ B,   // [64]
    float* __restrict__ Y)         // [N][64]
{
    constexpr int NG  = F / 4;
    constexpr int WST = 164;
    extern __shared__ float sm[];
    float* Xs  = sm;            // F*128
    float* WsD = sm + F * 128;  // F*WST

    const int tid = threadIdx.x;
    const int tr  = tid & 15;
    const int tc  = tid >> 4;
    const int rowBase = blockIdx.x * 128;

    // ---- stage W duplicated, staggered groups ----
    for (int i = tid; i < 64 * F; i += 128) {
        int j = i / F;
        int k = i - j * F;
        float w = W[i];
        int off = k * WST + (j >> 3) * 20 + (j & 7) * 2;
        WsD[off]     = w;
        WsD[off + 1] = w;
    }

    // ---- stage X transposed + swizzled (coalesced global reads) ----
    {
        const float4* X4 = reinterpret_cast<const float4*>(X);
        for (int i = tid; i < 128 * NG; i += 128) {
            int r = i / NG;
            int g = i - r * NG;
            int row = rowBase + r;
            float4 v = make_float4(0.f, 0.f, 0.f, 0.f);
            if (row < N) v = X4[(size_t)row * NG + g];
            int col = r ^ (2 * (g & 15));
            Xs[(4 * g + 0) * 128 + col] = v.x;
            Xs[(4 * g + 1) * 128 + col] = v.y;
            Xs[(4 * g + 2) * 128 + col] = v.z;
            Xs[(4 * g + 3) * 128 + col] = v.w;
        }
    }
    __syncthreads();

    // ---- accumulators: 4 row-pairs x 8 cols, bias in both lanes ----
    unsigned long long acc[4][8];
#pragma unroll
    for (int c = 0; c < 8; c++) {
        unsigned long long b2 = pack2(B[tc * 8 + c]);
#pragma unroll
        for (int j = 0; j < 4; j++) acc[j][c] = b2;
    }

    // ---- main loop ----
#pragma unroll 16
    for (int k = 0; k < F; k++) {
        const int m = 2 * ((k >> 2) & 15);
        unsigned long long x2[4];
#pragma unroll
        for (int j = 0; j < 4; j++)
            x2[j] = *reinterpret_cast<const unsigned long long*>(
                        &Xs[k * 128 + 32 * j + (((2 * tr)) ^ m)]);
        const ulonglong2* wp =
            reinterpret_cast<const ulonglong2*>(&WsD[k * WST + tc * 20]);
        ulonglong2 wA = wp[0], wB = wp[1], wC = wp[2], wD = wp[3];
        unsigned long long wv[8] = {wA.x, wA.y, wB.x, wB.y, wC.x, wC.y, wD.x, wD.y};
#pragma unroll
        for (int j = 0; j < 4; j++) {
#pragma unroll
            for (int c = 0; c < 8; c++)
                acc[j][c] = fma2(x2[j], wv[c], acc[j][c]);
        }
    }

    // ---- epilogue ----
#pragma unroll
    for (int j = 0; j < 4; j++) {
        float lo[8], hi[8];
#pragma unroll
        for (int c = 0; c < 8; c++) {
            unpack2(acc[j][c], lo[c], hi[c]);
            if (RELU) { lo[c] = fmaxf(lo[c], 0.f); hi[c] = fmaxf(hi[c], 0.f); }
        }
        const int row0 = rowBase + 32 * j + 2 * tr;
        if (row0 < N) {
            float4* p = reinterpret_cast<float4*>(Y + (size_t)row0 * 64 + tc * 8);
            p[0] = make_float4(lo[0], lo[1], lo[2], lo[3]);
            p[1] = make_float4(lo[4], lo[5], lo[6], lo[7]);
        }
        if (row0 + 1 < N) {
            float4* p = reinterpret_cast<float4*>(Y + (size_t)(row0 + 1) * 64 + tc * 8);
            p[0] = make_float4(hi[0], hi[1], hi[2], hi[3]);
            p[1] = make_float4(hi[4], hi[5], hi[6], hi[7]);
        }
    }
}

// ---------------------------------------------------------------------------
// Small-N fallback GEMM (F=48, N=1000)
// ---------------------------------------------------------------------------
template <int F, bool RELU>
__global__ void __launch_bounds__(128) gemm_small(
    const float* __restrict__ X, int N,
    const float* __restrict__ W, const float* __restrict__ B,
    float* __restrict__ Y)
{
    __shared__ float Wt[F * 64];
    __shared__ float Bs[64];
    const int tid = threadIdx.x;
    for (int i = tid; i < F * 64; i += 128) {
        int j = i / F;
        int k = i - j * F;
        Wt[k * 64 + j] = W[i];
    }
    if (tid < 64) Bs[tid] = B[tid];
    __syncthreads();

    const int row = blockIdx.x * 128 + tid;
    if (row >= N) return;

    float4 acc[16];
    const float4* Bs4 = reinterpret_cast<const float4*>(Bs);
#pragma unroll
    for (int j = 0; j < 16; j++) acc[j] = Bs4[j];

    const float4* X4  = reinterpret_cast<const float4*>(X + (size_t)row * F);
    const float4* Wt4 = reinterpret_cast<const float4*>(Wt);
#pragma unroll 2
    for (int k4 = 0; k4 < F / 4; k4++) {
        const float4 xv = X4[k4];
#pragma unroll
        for (int kk = 0; kk < 4; kk++) {
            const float xs = (kk == 0) ? xv.x : (kk == 1) ? xv.y : (kk == 2) ? xv.z : xv.w;
            const float4* wrow = Wt4 + (size_t)(k4 * 4 + kk) * 16;
#pragma unroll
            for (int j = 0; j < 16; j++) {
                float4 w = wrow[j];
                acc[j].x += xs * w.x;
                acc[j].y += xs * w.y;
                acc[j].z += xs * w.z;
                acc[j].w += xs * w.w;
            }
        }
    }
    float4* Y4 = reinterpret_cast<float4*>(Y + (size_t)row * 64);
#pragma unroll
    for (int j = 0; j < 16; j++) {
        float4 v = acc[j];
        if (RELU) {
            v.x = fmaxf(v.x, 0.f); v.y = fmaxf(v.y, 0.f);
            v.z = fmaxf(v.z, 0.f); v.w = fmaxf(v.w, 0.f);
        }
        Y4[j] = v;
    }
}

// agg[dst] += T[src] over edges, 16 threads (one float4 lane each) per edge.
__global__ void scatter_kernel(const int* __restrict__ src, const int* __restrict__ dst,
                               int E, const float4* __restrict__ T,
                               float4* __restrict__ agg)
{
    const int gid = blockIdx.x * blockDim.x + threadIdx.x;
    if (gid >= E * 16) return;
    const int e = gid >> 4;
    const int l = gid & 15;
    const int s = src[e];
    const int d = dst[e];
    const float4 v = T[(size_t)s * 16 + l];
    float4* p = agg + (size_t)d * 16 + l;
    asm volatile("red.global.add.v4.f32 [%0], {%1, %2, %3, %4};"
                 :: "l"(p), "f"(v.x), "f"(v.y), "f"(v.z), "f"(v.w)
                 : "memory");
}

extern "C" void kernel_launch(void* const* d_in, const int* in_sizes, int n_in,
                              void* d_out, int out_size)
{
    const float* x      = (const float*)d_in[0];
    const float* c      = (const float*)d_in[1];
    const float* r      = (const float*)d_in[2];
    const int*   e_xx_s = (const int*)d_in[3];
    const int*   e_xx_d = (const int*)d_in[4];
    const int*   e_cx_s = (const int*)d_in[5];
    const int*   e_cx_d = (const int*)d_in[6];
    const int*   e_rx_s = (const int*)d_in[7];
    const int*   e_rx_d = (const int*)d_in[8];
    const float* W_x    = (const float*)d_in[9];
    const float* b_x    = (const float*)d_in[10];
    const float* W_c    = (const float*)d_in[11];
    const float* b_c    = (const float*)d_in[12];
    const float* W_r    = (const float*)d_in[13];
    const float* b_r    = (const float*)d_in[14];
    const float* W_xx   = (const float*)d_in[15];
    const float* b_xx   = (const float*)d_in[16];
    const float* W_cx   = (const float*)d_in[17];
    const float* b_cx   = (const float*)d_in[18];
    const float* W_rx   = (const float*)d_in[19];
    const float* b_rx   = (const float*)d_in[20];
    const float* W_pool = (const float*)d_in[21];
    const float* b_pool = (const float*)d_in[22];

    const int nx  = in_sizes[0] / 64;
    const int nc  = in_sizes[1] / 32;
    const int nr  = in_sizes[2] / 48;
    const int Exx = in_sizes[3];
    const int Ecx = in_sizes[5];
    const int Erx = in_sizes[7];

    float *agg, *txx, *tcx, *trx;
    cudaGetSymbolAddress((void**)&agg, g_agg);
    cudaGetSymbolAddress((void**)&txx, g_txx);
    cudaGetSymbolAddress((void**)&tcx, g_tcx);
    cudaGetSymbolAddress((void**)&trx, g_trx);

    float* out   = (float*)d_out;
    float* x_out = out;
    float* c_out = out + (size_t)nx * 64;
    float* r_out = out + (size_t)nx * 64 + (size_t)nc * 64;

    const int gx = (nx + 127) / 128;
    const int gc = (nc + 127) / 128;
    const int gr = (nr + 127) / 128;

    constexpr int SM64 = (64 * 128 + 64 * 164) * 4;   // 74752 B
    constexpr int SM32 = (32 * 128 + 32 * 164) * 4;   // 37376 B

    cudaFuncSetAttribute((const void*)gemm_v3<64, true>,
                         cudaFuncAttributeMaxDynamicSharedMemorySize, SM64);
    cudaFuncSetAttribute((const void*)gemm_v3<64, false>,
                         cudaFuncAttributeMaxDynamicSharedMemorySize, SM64);

    // Per-node transforms (self-loop term initializes agg)
    gemm_v3<64, true ><<<gx, 128, SM64>>>(x, nx, W_x,  b_x,  agg);
    gemm_v3<64, true ><<<gx, 128, SM64>>>(x, nx, W_xx, b_xx, txx);
    gemm_v3<32, true ><<<gc, 128, SM32>>>(c, nc, W_cx, b_cx, tcx);
    gemm_v3<32, true ><<<gc, 128, SM32>>>(c, nc, W_c,  b_c,  c_out);
    gemm_small<48, true ><<<gr, 128>>>(r, nr, W_rx, b_rx, trx);
    gemm_small<48, true ><<<gr, 128>>>(r, nr, W_r,  b_r,  r_out);

    // Edge scatter-adds into agg
    scatter_kernel<<<((long long)Exx * 16 + 255) / 256, 256>>>(e_xx_s, e_xx_d, Exx,
                                                               (const float4*)txx, (float4*)agg);
    scatter_kernel<<<((long long)Ecx * 16 + 255) / 256, 256>>>(e_cx_s, e_cx_d, Ecx,
                                                               (const float4*)tcx, (float4*)agg);
    scatter_kernel<<<((long long)Erx * 16 + 255) / 256, 256>>>(e_rx_s, e_rx_d, Erx,
                                                               (const float4*)trx, (float4*)agg);

    // Output projection (no relu)
    gemm_v3<64, false><<<gx, 128, SM64>>>(agg, nx, W_pool, b_pool, x_out);
}

// round 4
// speedup vs baseline: 1.1737x; 1.0604x over previous
#include <cuda_runtime.h>

#define NX_MAX 100000
#define NC_MAX 50000
#define NR_MAX 1000
#define HID 64
#define EMAX 4200000

__device__ float g_agg[(size_t)NX_MAX * HID];
__device__ float g_txx[(size_t)NX_MAX * HID];
__device__ float g_tcx[(size_t)NC_MAX * HID];
__device__ float g_trx[(size_t)NR_MAX * HID];
__device__ int   g_off[NX_MAX + 1];
__device__ int   g_cur[NX_MAX];
__device__ int   g_bsum[256];
__device__ unsigned int g_eidx[EMAX];

// ---------- packed f32x2 helpers (sm_103a) ----------
__device__ __forceinline__ unsigned long long pack2(float x) {
    unsigned long long r;
    asm("mov.b64 %0, {%1, %1};" : "=l"(r) : "f"(x));
    return r;
}
__device__ __forceinline__ unsigned long long fma2(unsigned long long a,
                                                   unsigned long long b,
                                                   unsigned long long c) {
    unsigned long long d;
    asm("fma.rn.f32x2 %0, %1, %2, %3;" : "=l"(d) : "l"(a), "l"(b), "l"(c));
    return d;
}
__device__ __forceinline__ unsigned long long add2(unsigned long long a,
                                                   unsigned long long b) {
    unsigned long long d;
    asm("add.rn.f32x2 %0, %1, %2;" : "=l"(d) : "l"(a), "l"(b));
    return d;
}
__device__ __forceinline__ void unpack2(unsigned long long v, float& lo, float& hi) {
    asm("mov.b64 {%0, %1}, %2;" : "=f"(lo), "=f"(hi) : "l"(v));
}

// ---------------------------------------------------------------------------
// gemm_v4: 128-row tile, 256 threads. Thread (tr=tid&31, tc=tid>>5) computes
// rows {64*j + 2*tr + 0/1 : j=0,1} x cols [8*tc, 8*tc+8) as f32x2 row-pairs.
// Warp == one tc -> W reads are pure LDS broadcasts. Xs transposed+swizzled.
// ---------------------------------------------------------------------------
template <int F, bool RELU>
__global__ void __launch_bounds__(256, 3) gemm_v4(
    const float* __restrict__ X, int N,
    const float* __restrict__ W,   // [64][F]
    const float* __restrict__ B,   // [64]
    float* __restrict__ Y)         // [N][64]
{
    constexpr int NG = F / 4;
    extern __shared__ float sm[];
    float* Xs  = sm;            // [F][128] swizzled
    float* WsD = sm + F * 128;  // [F][128] duplicated (w,w)

    const int tid = threadIdx.x;
    const int tr  = tid & 31;
    const int tc  = tid >> 5;
    const int rowBase = blockIdx.x * 128;

    // stage W duplicated
    for (int i = tid; i < 64 * F; i += 256) {
        int j = i / F;
        int k = i - j * F;
        float w = W[i];
        WsD[k * 128 + j * 2]     = w;
        WsD[k * 128 + j * 2 + 1] = w;
    }
    // stage X transposed + swizzled
    {
        const float4* X4 = reinterpret_cast<const float4*>(X);
        for (int i = tid; i < 128 * NG; i += 256) {
            int r = i / NG;
            int g = i - r * NG;
            int row = rowBase + r;
            float4 v = make_float4(0.f, 0.f, 0.f, 0.f);
            if (row < N) v = X4[(size_t)row * NG + g];
            int col = r ^ (2 * (g & 15));
            Xs[(4 * g + 0) * 128 + col] = v.x;
            Xs[(4 * g + 1) * 128 + col] = v.y;
            Xs[(4 * g + 2) * 128 + col] = v.z;
            Xs[(4 * g + 3) * 128 + col] = v.w;
        }
    }
    __syncthreads();

    unsigned long long acc[2][8];
#pragma unroll
    for (int c = 0; c < 8; c++) {
        unsigned long long b2 = pack2(B[tc * 8 + c]);
        acc[0][c] = b2;
        acc[1][c] = b2;
    }

#pragma unroll 16
    for (int k = 0; k < F; k++) {
        const int m = 2 * ((k >> 2) & 15);
        unsigned long long x0 = *reinterpret_cast<const unsigned long long*>(
            &Xs[k * 128 + ((2 * tr) ^ m)]);
        unsigned long long x1 = *reinterpret_cast<const unsigned long long*>(
            &Xs[k * 128 + 64 + ((2 * tr) ^ m)]);
        const ulonglong2* wp =
            reinterpret_cast<const ulonglong2*>(&WsD[k * 128 + tc * 16]);
        ulonglong2 wA = wp[0], wB = wp[1], wC = wp[2], wD = wp[3];
        unsigned long long wv[8] = {wA.x, wA.y, wB.x, wB.y, wC.x, wC.y, wD.x, wD.y};
#pragma unroll
        for (int c = 0; c < 8; c++) {
            acc[0][c] = fma2(x0, wv[c], acc[0][c]);
            acc[1][c] = fma2(x1, wv[c], acc[1][c]);
        }
    }

#pragma unroll
    for (int j = 0; j < 2; j++) {
        float lo[8], hi[8];
#pragma unroll
        for (int c = 0; c < 8; c++) {
            unpack2(acc[j][c], lo[c], hi[c]);
            if (RELU) { lo[c] = fmaxf(lo[c], 0.f); hi[c] = fmaxf(hi[c], 0.f); }
        }
        const int row0 = rowBase + 64 * j + 2 * tr;
        if (row0 < N) {
            float4* p = reinterpret_cast<float4*>(Y + (size_t)row0 * 64 + tc * 8);
            p[0] = make_float4(lo[0], lo[1], lo[2], lo[3]);
            p[1] = make_float4(lo[4], lo[5], lo[6], lo[7]);
        }
        if (row0 + 1 < N) {
            float4* p = reinterpret_cast<float4*>(Y + (size_t)(row0 + 1) * 64 + tc * 8);
            p[0] = make_float4(hi[0], hi[1], hi[2], hi[3]);
            p[1] = make_float4(hi[4], hi[5], hi[6], hi[7]);
        }
    }
}

// ---------------- small GEMM for r (F=48, N=1000) ----------------
template <int F, bool RELU>
__global__ void __launch_bounds__(128) gemm_small(
    const float* __restrict__ X, int N,
    const float* __restrict__ W, const float* __restrict__ B,
    float* __restrict__ Y)
{
    __shared__ float Wt[F * 64];
    __shared__ float Bs[64];
    const int tid = threadIdx.x;
    for (int i = tid; i < F * 64; i += 128) {
        int j = i / F;
        int k = i - j * F;
        Wt[k * 64 + j] = W[i];
    }
    if (tid < 64) Bs[tid] = B[tid];
    __syncthreads();
    const int row = blockIdx.x * 128 + tid;
    if (row >= N) return;
    float4 acc[16];
    const float4* Bs4 = reinterpret_cast<const float4*>(Bs);
#pragma unroll
    for (int j = 0; j < 16; j++) acc[j] = Bs4[j];
    const float4* X4  = reinterpret_cast<const float4*>(X + (size_t)row * F);
    const float4* Wt4 = reinterpret_cast<const float4*>(Wt);
#pragma unroll 2
    for (int k4 = 0; k4 < F / 4; k4++) {
        const float4 xv = X4[k4];
#pragma unroll
        for (int kk = 0; kk < 4; kk++) {
            const float xs = (kk == 0) ? xv.x : (kk == 1) ? xv.y : (kk == 2) ? xv.z : xv.w;
            const float4* wrow = Wt4 + (size_t)(k4 * 4 + kk) * 16;
#pragma unroll
            for (int j = 0; j < 16; j++) {
                float4 w = wrow[j];
                acc[j].x += xs * w.x; acc[j].y += xs * w.y;
                acc[j].z += xs * w.z; acc[j].w += xs * w.w;
            }
        }
    }
    float4* Y4 = reinterpret_cast<float4*>(Y + (size_t)row * 64);
#pragma unroll
    for (int j = 0; j < 16; j++) {
        float4 v = acc[j];
        if (RELU) {
            v.x = fmaxf(v.x, 0.f); v.y = fmaxf(v.y, 0.f);
            v.z = fmaxf(v.z, 0.f); v.w = fmaxf(v.w, 0.f);
        }
        Y4[j] = v;
    }
}

// ---------------- CSR build ----------------
__global__ void zero_kernel(int* p, int n) {
    int i = blockIdx.x * blockDim.x + threadIdx.x;
    if (i < n) p[i] = 0;
}

__global__ void hist_kernel(const int* __restrict__ dxx, const int* __restrict__ dcx,
                            const int* __restrict__ drx,
                            int Exx, int Ecx, int Erx, int* __restrict__ deg)
{
    int i = blockIdx.x * blockDim.x + threadIdx.x;
    int Etot = Exx + Ecx + Erx;
    if (i >= Etot) return;
    int d;
    if (i < Exx) d = dxx[i];
    else if (i < Exx + Ecx) d = dcx[i - Exx];
    else d = drx[i - Exx - Ecx];
    atomicAdd(&deg[d], 1);
}

// scan phase 1: per-block (1024) exclusive scan of deg -> off, block totals -> bsum
__global__ void scan1_kernel(const int* __restrict__ deg, int* __restrict__ off,
                             int* __restrict__ bsum, int n)
{
    __shared__ int s[1024];
    int t = threadIdx.x;
    int i = blockIdx.x * 1024 + t;
    int v = (i < n) ? deg[i] : 0;
    s[t] = v;
    __syncthreads();
#pragma unroll
    for (int o = 1; o < 1024; o <<= 1) {
        int a = (t >= o) ? s[t - o] : 0;
        __syncthreads();
        s[t] += a;
        __syncthreads();
    }
    if (i < n) off[i] = s[t] - v;               // exclusive
    if (t == 1023) bsum[blockIdx.x] = s[1023];  // block total
}

// scan phase 2: single-thread exclusive scan of block sums; writes off[n]=Etot
__global__ void scan2_kernel(int* __restrict__ bsum, int nb, int* __restrict__ off,
                             int n, int Etot)
{
    if (threadIdx.x == 0 && blockIdx.x == 0) {
        int run = 0;
        for (int b = 0; b < nb; b++) {
            int v = bsum[b];
            bsum[b] = run;
            run += v;
        }
        off[n] = Etot;
    }
}

// scan phase 3: add block offsets, init cursors
__global__ void scan3_kernel(int* __restrict__ off, const int* __restrict__ bsum,
                             int* __restrict__ cur, int n)
{
    int i = blockIdx.x * 1024 + threadIdx.x;
    if (i < n) {
        int o = off[i] + bsum[blockIdx.x];
        off[i] = o;
        cur[i] = o;
    }
}

// fill: place (rel,src) records into CSR slots
__global__ void fill_kernel(const int* __restrict__ sxx, const int* __restrict__ dxx,
                            const int* __restrict__ scx, const int* __restrict__ dcx,
                            const int* __restrict__ srx, const int* __restrict__ drx,
                            int Exx, int Ecx, int Erx,
                            int* __restrict__ cur, unsigned int* __restrict__ eidx)
{
    int i = blockIdx.x * blockDim.x + threadIdx.x;
    int Etot = Exx + Ecx + Erx;
    if (i >= Etot) return;
    int d, s; unsigned int rel;
    if (i < Exx)            { d = dxx[i];             s = sxx[i];             rel = 0u; }
    else if (i < Exx + Ecx) { d = dcx[i - Exx];       s = scx[i - Exx];       rel = 1u; }
    else                    { d = drx[i - Exx - Ecx]; s = srx[i - Exx - Ecx]; rel = 2u; }
    int p = atomicAdd(&cur[d], 1);
    eidx[p] = (rel << 28) | (unsigned int)s;
}

// ---------------- gather-accumulate: one warp per dst row ----------------
__global__ void __launch_bounds__(256) gather_accum(
    const float* __restrict__ txx, const float* __restrict__ tcx,
    const float* __restrict__ trx,
    float* __restrict__ agg,      // in: self-loop term; out: full aggregate
    const int* __restrict__ off, const unsigned int* __restrict__ eidx,
    int nx)
{
    const int warp = (blockIdx.x * 256 + threadIdx.x) >> 5;
    const int lane = threadIdx.x & 31;
    if (warp >= nx) return;
    const int d = warp;
    const int s = off[d];
    const int e = off[d + 1];

    unsigned long long acc = *reinterpret_cast<const unsigned long long*>(
        agg + (size_t)d * 64 + lane * 2);

    int i = s;
    for (; i + 4 <= e; i += 4) {
        unsigned int r0 = eidx[i], r1 = eidx[i + 1], r2 = eidx[i + 2], r3 = eidx[i + 3];
        const float* t0 = (r0 >> 28) == 0 ? txx : ((r0 >> 28) == 1 ? tcx : trx);
        const float* t1 = (r1 >> 28) == 0 ? txx : ((r1 >> 28) == 1 ? tcx : trx);
        const float* t2 = (r2 >> 28) == 0 ? txx : ((r2 >> 28) == 1 ? tcx : trx);
        const float* t3 = (r3 >> 28) == 0 ? txx : ((r3 >> 28) == 1 ? tcx : trx);
        unsigned long long v0 = *reinterpret_cast<const unsigned long long*>(
            t0 + (size_t)(r0 & 0x0FFFFFFFu) * 64 + lane * 2);
        unsigned long long v1 = *reinterpret_cast<const unsigned long long*>(
            t1 + (size_t)(r1 & 0x0FFFFFFFu) * 64 + lane * 2);
        unsigned long long v2 = *reinterpret_cast<const unsigned long long*>(
            t2 + (size_t)(r2 & 0x0FFFFFFFu) * 64 + lane * 2);
        unsigned long long v3 = *reinterpret_cast<const unsigned long long*>(
            t3 + (size_t)(r3 & 0x0FFFFFFFu) * 64 + lane * 2);
        acc = add2(acc, v0);
        acc = add2(acc, v1);
        acc = add2(acc, v2);
        acc = add2(acc, v3);
    }
    for (; i < e; i++) {
        unsigned int r0 = eidx[i];
        const float* t0 = (r0 >> 28) == 0 ? txx : ((r0 >> 28) == 1 ? tcx : trx);
        unsigned long long v0 = *reinterpret_cast<const unsigned long long*>(
            t0 + (size_t)(r0 & 0x0FFFFFFFu) * 64 + lane * 2);
        acc = add2(acc, v0);
    }

    *reinterpret_cast<unsigned long long*>(agg + (size_t)d * 64 + lane * 2) = acc;
}

extern "C" void kernel_launch(void* const* d_in, const int* in_sizes, int n_in,
                              void* d_out, int out_size)
{
    const float* x      = (const float*)d_in[0];
    const float* c      = (const float*)d_in[1];
    const float* r      = (const float*)d_in[2];
    const int*   e_xx_s = (const int*)d_in[3];
    const int*   e_xx_d = (const int*)d_in[4];
    const int*   e_cx_s = (const int*)d_in[5];
    const int*   e_cx_d = (const int*)d_in[6];
    const int*   e_rx_s = (const int*)d_in[7];
    const int*   e_rx_d = (const int*)d_in[8];
    const float* W_x    = (const float*)d_in[9];
    const float* b_x    = (const float*)d_in[10];
    const float* W_c    = (const float*)d_in[11];
    const float* b_c    = (const float*)d_in[12];
    const float* W_r    = (const float*)d_in[13];
    const float* b_r    = (const float*)d_in[14];
    const float* W_xx   = (const float*)d_in[15];
    const float* b_xx   = (const float*)d_in[16];
    const float* W_cx   = (const float*)d_in[17];
    const float* b_cx   = (const float*)d_in[18];
    const float* W_rx   = (const float*)d_in[19];
    const float* b_rx   = (const float*)d_in[20];
    const float* W_pool = (const float*)d_in[21];
    const float* b_pool = (const float*)d_in[22];

    const int nx  = in_sizes[0] / 64;
    const int nc  = in_sizes[1] / 32;
    const int nr  = in_sizes[2] / 48;
    const int Exx = in_sizes[3];
    const int Ecx = in_sizes[5];
    const int Erx = in_sizes[7];
    const int Etot = Exx + Ecx + Erx;

    float *agg, *txx, *tcx, *trx;
    int *off, *cur, *bsum;
    unsigned int* eidx;
    cudaGetSymbolAddress((void**)&agg,  g_agg);
    cudaGetSymbolAddress((void**)&txx,  g_txx);
    cudaGetSymbolAddress((void**)&tcx,  g_tcx);
    cudaGetSymbolAddress((void**)&trx,  g_trx);
    cudaGetSymbolAddress((void**)&off,  g_off);
    cudaGetSymbolAddress((void**)&cur,  g_cur);
    cudaGetSymbolAddress((void**)&bsum, g_bsum);
    cudaGetSymbolAddress((void**)&eidx, g_eidx);

    float* out   = (float*)d_out;
    float* x_out = out;
    float* c_out = out + (size_t)nx * 64;
    float* r_out = out + (size_t)nx * 64 + (size_t)nc * 64;

    const int gx = (nx + 127) / 128;
    const int gc = (nc + 127) / 128;
    const int gr = (nr + 127) / 128;
    const int nb = (nx + 1023) / 1024;

    constexpr int SM64 = (64 * 128 + 64 * 128) * 4;   // 65536 B
    constexpr int SM32 = (32 * 128 + 32 * 128) * 4;   // 32768 B
    cudaFuncSetAttribute((const void*)gemm_v4<64, true>,
                         cudaFuncAttributeMaxDynamicSharedMemorySize, SM64);
    cudaFuncSetAttribute((const void*)gemm_v4<64, false>,
                         cudaFuncAttributeMaxDynamicSharedMemorySize, SM64);

    // ---- CSR build ----
    zero_kernel<<<(nx + 255) / 256, 256>>>(off, nx);   // use off[] as deg scratch? no: deg in cur
    // deg lives in cur initially: zero cur, histogram into cur
    zero_kernel<<<(nx + 255) / 256, 256>>>(cur, nx);
    hist_kernel<<<(Etot + 255) / 256, 256>>>(e_xx_d, e_cx_d, e_rx_d, Exx, Ecx, Erx, cur);
    scan1_kernel<<<nb, 1024>>>(cur, off, bsum, nx);
    scan2_kernel<<<1, 32>>>(bsum, nb, off, nx, Etot);
    scan3_kernel<<<nb, 1024>>>(off, bsum, cur, nx);
    fill_kernel<<<(Etot + 255) / 256, 256>>>(e_xx_s, e_xx_d, e_cx_s, e_cx_d,
                                             e_rx_s, e_rx_d, Exx, Ecx, Erx, cur, eidx);

    // ---- per-node transforms ----
    gemm_v4<64, true ><<<gx, 256, SM64>>>(x, nx, W_x,  b_x,  agg);   // self-loop -> agg
    gemm_v4<64, true ><<<gx, 256, SM64>>>(x, nx, W_xx, b_xx, txx);
    gemm_v4<32, true ><<<gc, 256, SM32>>>(c, nc, W_cx, b_cx, tcx);
    gemm_v4<32, true ><<<gc, 256, SM32>>>(c, nc, W_c,  b_c,  c_out);
    gemm_small<48, true ><<<gr, 128>>>(r, nr, W_rx, b_rx, trx);
    gemm_small<48, true ><<<gr, 128>>>(r, nr, W_r,  b_r,  r_out);

    // ---- aggregate (no atomics) ----
    gather_accum<<<(nx + 7) / 8, 256>>>(txx, tcx, trx, agg, off, eidx, nx);

    // ---- output projection ----
    gemm_v4<64, false><<<gx, 256, SM64>>>(agg, nx, W_pool, b_pool, x_out);
}

// round 6
// speedup vs baseline: 1.5709x; 1.3384x over previous
#include <cuda_runtime.h>
#include <cuda_bf16.h>
#include <cstdint>

#define NX_MAX 100000
#define NC_MAX 50000
#define NR_MAX 1000
#define HID 64
#define EMAX 4200000

__device__ float g_agg[(size_t)NX_MAX * HID];
__device__ float g_txx[(size_t)NX_MAX * HID];
__device__ float g_tcx[(size_t)NC_MAX * HID];
__device__ float g_trx[(size_t)NR_MAX * HID];
__device__ int   g_off[NX_MAX + 1];
__device__ int   g_cur[NX_MAX];
__device__ int   g_bsum[256];
__device__ unsigned int g_eidx[EMAX];

// ---------- helpers ----------
__device__ __forceinline__ uint32_t smem_to_u32(const void* p) {
    uint32_t a;
    asm("{ .reg .u64 t; cvta.to.shared.u64 t, %1; cvt.u32.u64 %0, t; }"
        : "=r"(a) : "l"(p));
    return a;
}
__device__ __forceinline__ unsigned long long add2(unsigned long long a,
                                                   unsigned long long b) {
    unsigned long long d;
    asm("add.rn.f32x2 %0, %1, %2;" : "=l"(d) : "l"(a), "l"(b));
    return d;
}

// split a float4 into bf16-hi (8B) and bf16-lo (8B) packed words
__device__ __forceinline__ void split4(const float4 v, unsigned long long& hi,
                                       unsigned long long& lo) {
    __nv_bfloat16 h0 = __float2bfloat16_rn(v.x);
    __nv_bfloat16 h1 = __float2bfloat16_rn(v.y);
    __nv_bfloat16 h2 = __float2bfloat16_rn(v.z);
    __nv_bfloat16 h3 = __float2bfloat16_rn(v.w);
    __nv_bfloat16 l0 = __float2bfloat16_rn(v.x - __bfloat162float(h0));
    __nv_bfloat16 l1 = __float2bfloat16_rn(v.y - __bfloat162float(h1));
    __nv_bfloat16 l2 = __float2bfloat16_rn(v.z - __bfloat162float(h2));
    __nv_bfloat16 l3 = __float2bfloat16_rn(v.w - __bfloat162float(h3));
    __nv_bfloat162 ha = __halves2bfloat162(h0, h1), hb = __halves2bfloat162(h2, h3);
    __nv_bfloat162 la = __halves2bfloat162(l0, l1), lb = __halves2bfloat162(l2, l3);
    hi = (unsigned long long)*reinterpret_cast<uint32_t*>(&ha) |
         ((unsigned long long)*reinterpret_cast<uint32_t*>(&hb) << 32);
    lo = (unsigned long long)*reinterpret_cast<uint32_t*>(&la) |
         ((unsigned long long)*reinterpret_cast<uint32_t*>(&lb) << 32);
}

__device__ __forceinline__ void ldsm_x4(uint32_t* r, uint32_t addr) {
    asm volatile("ldmatrix.sync.aligned.m8n8.x4.shared.b16 {%0,%1,%2,%3}, [%4];"
                 : "=r"(r[0]), "=r"(r[1]), "=r"(r[2]), "=r"(r[3]) : "r"(addr));
}
__device__ __forceinline__ void mma16816(float* c, const uint32_t* a,
                                         uint32_t b0, uint32_t b1) {
    asm volatile(
        "mma.sync.aligned.m16n8k16.row.col.f32.bf16.bf16.f32 "
        "{%0,%1,%2,%3}, {%4,%5,%6,%7}, {%8,%9}, {%0,%1,%2,%3};"
        : "+f"(c[0]), "+f"(c[1]), "+f"(c[2]), "+f"(c[3])
        : "r"(a[0]), "r"(a[1]), "r"(a[2]), "r"(a[3]), "r"(b0), "r"(b1));
}

// ---------------------------------------------------------------------------
// hmma_gemm: Y[128-row tile][64] = (relu?)(X[.,F] @ W[64,F]^T + B) via
// mma.sync bf16x2 split (hi*hi + hi*lo + lo*hi), fp32 accumulate.
// 256 threads = 8 warps; warp w computes rows [16w,16w+16) x 64 cols.
// Smem tiles: 128-byte row stride, XOR-by-(row&7)<<4 swizzle (ldmatrix-safe).
// ---------------------------------------------------------------------------
#define SOFF_AH 0
#define SOFF_AL 16384
#define SOFF_WH 32768
#define SOFF_WL 40960
#define SOFF_BI 49152
#define SMEM_HM 49408

template <int F, bool RELU>
__global__ void __launch_bounds__(256) hmma_gemm(
    const float* __restrict__ X, int N,
    const float* __restrict__ W,   // [64][F]
    const float* __restrict__ B,   // [64]
    float* __restrict__ Y)         // [N][64]
{
    constexpr int NG = F / 4;      // float4 per row
    constexpr int KS = F / 16;     // k-steps

    extern __shared__ char smem[];
    const uint32_t sb = smem_to_u32(smem);
    const int tid  = threadIdx.x;
    const int wid  = tid >> 5;
    const int lane = tid & 31;
    const int rowBase = blockIdx.x * 128;

    // ---- stage bias ----
    if (tid < 64) *reinterpret_cast<float*>(smem + SOFF_BI + tid * 4) = B[tid];

    // ---- stage A (X tile) split hi/lo, swizzled ----
    {
        const float4* X4 = reinterpret_cast<const float4*>(X);
        for (int i = tid; i < 128 * NG; i += 256) {
            int r = i / NG;
            int g = i - r * NG;
            int row = rowBase + r;
            float4 v = make_float4(0.f, 0.f, 0.f, 0.f);
            if (row < N) v = X4[(size_t)row * NG + g];
            unsigned long long hi, lo;
            split4(v, hi, lo);
            uint32_t off = r * 128 + ((g * 8) ^ ((r & 7) << 4));
            *reinterpret_cast<unsigned long long*>(smem + SOFF_AH + off) = hi;
            *reinterpret_cast<unsigned long long*>(smem + SOFF_AL + off) = lo;
        }
    }
    // ---- stage W split hi/lo, swizzled ----
    {
        const float4* W4 = reinterpret_cast<const float4*>(W);
        for (int i = tid; i < 64 * NG; i += 256) {
            int n = i / NG;
            int g = i - n * NG;
            float4 v = W4[(size_t)n * NG + g];
            unsigned long long hi, lo;
            split4(v, hi, lo);
            uint32_t off = n * 128 + ((g * 8) ^ ((n & 7) << 4));
            *reinterpret_cast<unsigned long long*>(smem + SOFF_WH + off) = hi;
            *reinterpret_cast<unsigned long long*>(smem + SOFF_WL + off) = lo;
        }
    }
    __syncthreads();

    // ---- per-lane ldmatrix addresses ----
    const int rA   = wid * 16 + (lane & 7) + ((lane >> 3) & 1) * 8;   // A row
    const uint32_t aOff  = ((lane >> 4) & 1) * 16;                    // k-half bytes
    const uint32_t aXor  = (rA & 7) << 4;
    const uint32_t aBaseH = sb + SOFF_AH + rA * 128;
    const uint32_t aBaseL = sb + SOFF_AL + rA * 128;

    uint32_t bBaseH[4], bBaseL[4], bXor[4];
    const uint32_t bOff = ((lane >> 3) & 1) * 16;
#pragma unroll
    for (int p = 0; p < 4; p++) {
        int n = p * 16 + ((lane >> 4) & 1) * 8 + (lane & 7);
        bXor[p]   = (n & 7) << 4;
        bBaseH[p] = sb + SOFF_WH + n * 128;
        bBaseL[p] = sb + SOFF_WL + n * 128;
    }

    float c[8][4];
#pragma unroll
    for (int nt = 0; nt < 8; nt++)
#pragma unroll
        for (int q = 0; q < 4; q++) c[nt][q] = 0.f;

    // ---- main loop ----
#pragma unroll
    for (int ks = 0; ks < KS; ks++) {
        uint32_t ah[4], al[4];
        ldsm_x4(ah, aBaseH + ((ks * 32 + aOff) ^ aXor));
        ldsm_x4(al, aBaseL + ((ks * 32 + aOff) ^ aXor));
#pragma unroll
        for (int p = 0; p < 4; p++) {
            uint32_t bh[4], bl[4];
            ldsm_x4(bh, bBaseH[p] + ((ks * 32 + bOff) ^ bXor[p]));
            ldsm_x4(bl, bBaseL[p] + ((ks * 32 + bOff) ^ bXor[p]));
            mma16816(c[2 * p],     ah, bh[0], bh[1]);
            mma16816(c[2 * p],     ah, bl[0], bl[1]);
            mma16816(c[2 * p],     al, bh[0], bh[1]);
            mma16816(c[2 * p + 1], ah, bh[2], bh[3]);
            mma16816(c[2 * p + 1], ah, bl[2], bl[3]);
            mma16816(c[2 * p + 1], al, bh[2], bh[3]);
        }
    }

    // ---- epilogue: bias + relu, direct float2 stores ----
    const int g = lane >> 2;
    const int t = lane & 3;
    const int row0 = rowBase + wid * 16 + g;
    const float* Bs = reinterpret_cast<const float*>(smem + SOFF_BI);
#pragma unroll
    for (int nt = 0; nt < 8; nt++) {
        int col = nt * 8 + 2 * t;
        float bx = Bs[col], by = Bs[col + 1];
        float v0 = c[nt][0] + bx, v1 = c[nt][1] + by;
        float v2 = c[nt][2] + bx, v3 = c[nt][3] + by;
        if (RELU) {
            v0 = fmaxf(v0, 0.f); v1 = fmaxf(v1, 0.f);
            v2 = fmaxf(v2, 0.f); v3 = fmaxf(v3, 0.f);
        }
        if (row0 < N)
            *reinterpret_cast<float2*>(Y + (size_t)row0 * 64 + col) =
                make_float2(v0, v1);
        if (row0 + 8 < N)
            *reinterpret_cast<float2*>(Y + (size_t)(row0 + 8) * 64 + col) =
                make_float2(v2, v3);
    }
}

// ---------------- small GEMM for r (F=48, N=1000) ----------------
template <int F, bool RELU>
__global__ void __launch_bounds__(128) gemm_small(
    const float* __restrict__ X, int N,
    const float* __restrict__ W, const float* __restrict__ B,
    float* __restrict__ Y)
{
    __shared__ float Wt[F * 64];
    __shared__ float Bs[64];
    const int tid = threadIdx.x;
    for (int i = tid; i < F * 64; i += 128) {
        int j = i / F;
        int k = i - j * F;
        Wt[k * 64 + j] = W[i];
    }
    if (tid < 64) Bs[tid] = B[tid];
    __syncthreads();
    const int row = blockIdx.x * 128 + tid;
    if (row >= N) return;
    float4 acc[16];
    const float4* Bs4 = reinterpret_cast<const float4*>(Bs);
#pragma unroll
    for (int j = 0; j < 16; j++) acc[j] = Bs4[j];
    const float4* X4  = reinterpret_cast<const float4*>(X + (size_t)row * F);
    const float4* Wt4 = reinterpret_cast<const float4*>(Wt);
#pragma unroll 2
    for (int k4 = 0; k4 < F / 4; k4++) {
        const float4 xv = X4[k4];
#pragma unroll
        for (int kk = 0; kk < 4; kk++) {
            const float xs = (kk == 0) ? xv.x : (kk == 1) ? xv.y : (kk == 2) ? xv.z : xv.w;
            const float4* wrow = Wt4 + (size_t)(k4 * 4 + kk) * 16;
#pragma unroll
            for (int j = 0; j < 16; j++) {
                float4 w = wrow[j];
                acc[j].x += xs * w.x; acc[j].y += xs * w.y;
                acc[j].z += xs * w.z; acc[j].w += xs * w.w;
            }
        }
    }
    float4* Y4 = reinterpret_cast<float4*>(Y + (size_t)row * 64);
#pragma unroll
    for (int j = 0; j < 16; j++) {
        float4 v = acc[j];
        if (RELU) {
            v.x = fmaxf(v.x, 0.f); v.y = fmaxf(v.y, 0.f);
            v.z = fmaxf(v.z, 0.f); v.w = fmaxf(v.w, 0.f);
        }
        Y4[j] = v;
    }
}

// ---------------- CSR build ----------------
__global__ void zero_kernel(int* p, int n) {
    int i = blockIdx.x * blockDim.x + threadIdx.x;
    if (i < n) p[i] = 0;
}

__global__ void hist_kernel(const int* __restrict__ dxx, const int* __restrict__ dcx,
                            const int* __restrict__ drx,
                            int Exx, int Ecx, int Erx, int* __restrict__ deg)
{
    int i = blockIdx.x * blockDim.x + threadIdx.x;
    int Etot = Exx + Ecx + Erx;
    if (i >= Etot) return;
    int d;
    if (i < Exx) d = dxx[i];
    else if (i < Exx + Ecx) d = dcx[i - Exx];
    else d = drx[i - Exx - Ecx];
    atomicAdd(&deg[d], 1);
}

__global__ void scan1_kernel(const int* __restrict__ deg, int* __restrict__ off,
                             int* __restrict__ bsum, int n)
{
    __shared__ int s[1024];
    int t = threadIdx.x;
    int i = blockIdx.x * 1024 + t;
    int v = (i < n) ? deg[i] : 0;
    s[t] = v;
    __syncthreads();
#pragma unroll
    for (int o = 1; o < 1024; o <<= 1) {
        int a = (t >= o) ? s[t - o] : 0;
        __syncthreads();
        s[t] += a;
        __syncthreads();
    }
    if (i < n) off[i] = s[t] - v;
    if (t == 1023) bsum[blockIdx.x] = s[1023];
}

__global__ void scan2_kernel(int* __restrict__ bsum, int nb, int* __restrict__ off,
                             int n, int Etot)
{
    if (threadIdx.x == 0 && blockIdx.x == 0) {
        int run = 0;
        for (int b = 0; b < nb; b++) {
            int v = bsum[b];
            bsum[b] = run;
            run += v;
        }
        off[n] = Etot;
    }
}

__global__ void scan3_kernel(int* __restrict__ off, const int* __restrict__ bsum,
                             int* __restrict__ cur, int n)
{
    int i = blockIdx.x * 1024 + threadIdx.x;
    if (i < n) {
        int o = off[i] + bsum[blockIdx.x];
        off[i] = o;
        cur[i] = o;
    }
}

__global__ void fill_kernel(const int* __restrict__ sxx, const int* __restrict__ dxx,
                            const int* __restrict__ scx, const int* __restrict__ dcx,
                            const int* __restrict__ srx, const int* __restrict__ drx,
                            int Exx, int Ecx, int Erx,
                            int* __restrict__ cur, unsigned int* __restrict__ eidx)
{
    int i = blockIdx.x * blockDim.x + threadIdx.x;
    int Etot = Exx + Ecx + Erx;
    if (i >= Etot) return;
    int d, s; unsigned int rel;
    if (i < Exx)            { d = dxx[i];             s = sxx[i];             rel = 0u; }
    else if (i < Exx + Ecx) { d = dcx[i - Exx];       s = scx[i - Exx];       rel = 1u; }
    else                    { d = drx[i - Exx - Ecx]; s = srx[i - Exx - Ecx]; rel = 2u; }
    int p = atomicAdd(&cur[d], 1);
    eidx[p] = (rel << 28) | (unsigned int)s;
}

// ---------------- gather-accumulate: one warp per dst row ----------------
__global__ void __launch_bounds__(256) gather_accum(
    const float* __restrict__ txx, const float* __restrict__ tcx,
    const float* __restrict__ trx,
    float* __restrict__ agg,
    const int* __restrict__ off, const unsigned int* __restrict__ eidx,
    int nx)
{
    const int warp = (blockIdx.x * 256 + threadIdx.x) >> 5;
    const int lane = threadIdx.x & 31;
    if (warp >= nx) return;
    const int d = warp;
    const int s = off[d];
    const int e = off[d + 1];

    unsigned long long acc = *reinterpret_cast<const unsigned long long*>(
        agg + (size_t)d * 64 + lane * 2);

    int i = s;
    for (; i + 4 <= e; i += 4) {
        unsigned int r0 = eidx[i], r1 = eidx[i + 1], r2 = eidx[i + 2], r3 = eidx[i + 3];
        const float* t0 = (r0 >> 28) == 0 ? txx : ((r0 >> 28) == 1 ? tcx : trx);
        const float* t1 = (r1 >> 28) == 0 ? txx : ((r1 >> 28) == 1 ? tcx : trx);
        const float* t2 = (r2 >> 28) == 0 ? txx : ((r2 >> 28) == 1 ? tcx : trx);
        const float* t3 = (r3 >> 28) == 0 ? txx : ((r3 >> 28) == 1 ? tcx : trx);
        unsigned long long v0 = *reinterpret_cast<const unsigned long long*>(
            t0 + (size_t)(r0 & 0x0FFFFFFFu) * 64 + lane * 2);
        unsigned long long v1 = *reinterpret_cast<const unsigned long long*>(
            t1 + (size_t)(r1 & 0x0FFFFFFFu) * 64 + lane * 2);
        unsigned long long v2 = *reinterpret_cast<const unsigned long long*>(
            t2 + (size_t)(r2 & 0x0FFFFFFFu) * 64 + lane * 2);
        unsigned long long v3 = *reinterpret_cast<const unsigned long long*>(
            t3 + (size_t)(r3 & 0x0FFFFFFFu) * 64 + lane * 2);
        acc = add2(acc, v0);
        acc = add2(acc, v1);
        acc = add2(acc, v2);
        acc = add2(acc, v3);
    }
    for (; i < e; i++) {
        unsigned int r0 = eidx[i];
        const float* t0 = (r0 >> 28) == 0 ? txx : ((r0 >> 28) == 1 ? tcx : trx);
        unsigned long long v0 = *reinterpret_cast<const unsigned long long*>(
            t0 + (size_t)(r0 & 0x0FFFFFFFu) * 64 + lane * 2);
        acc = add2(acc, v0);
    }

    *reinterpret_cast<unsigned long long*>(agg + (size_t)d * 64 + lane * 2) = acc;
}

extern "C" void kernel_launch(void* const* d_in, const int* in_sizes, int n_in,
                              void* d_out, int out_size)
{
    const float* x      = (const float*)d_in[0];
    const float* c      = (const float*)d_in[1];
    const float* r      = (const float*)d_in[2];
    const int*   e_xx_s = (const int*)d_in[3];
    const int*   e_xx_d = (const int*)d_in[4];
    const int*   e_cx_s = (const int*)d_in[5];
    const int*   e_cx_d = (const int*)d_in[6];
    const int*   e_rx_s = (const int*)d_in[7];
    const int*   e_rx_d = (const int*)d_in[8];
    const float* W_x    = (const float*)d_in[9];
    const float* b_x    = (const float*)d_in[10];
    const float* W_c    = (const float*)d_in[11];
    const float* b_c    = (const float*)d_in[12];
    const float* W_r    = (const float*)d_in[13];
    const float* b_r    = (const float*)d_in[14];
    const float* W_xx   = (const float*)d_in[15];
    const float* b_xx   = (const float*)d_in[16];
    const float* W_cx   = (const float*)d_in[17];
    const float* b_cx   = (const float*)d_in[18];
    const float* W_rx   = (const float*)d_in[19];
    const float* b_rx   = (const float*)d_in[20];
    const float* W_pool = (const float*)d_in[21];
    const float* b_pool = (const float*)d_in[22];

    const int nx  = in_sizes[0] / 64;
    const int nc  = in_sizes[1] / 32;
    const int nr  = in_sizes[2] / 48;
    const int Exx = in_sizes[3];
    const int Ecx = in_sizes[5];
    const int Erx = in_sizes[7];
    const int Etot = Exx + Ecx + Erx;

    float *agg, *txx, *tcx, *trx;
    int *off, *cur, *bsum;
    unsigned int* eidx;
    cudaGetSymbolAddress((void**)&agg,  g_agg);
    cudaGetSymbolAddress((void**)&txx,  g_txx);
    cudaGetSymbolAddress((void**)&tcx,  g_tcx);
    cudaGetSymbolAddress((void**)&trx,  g_trx);
    cudaGetSymbolAddress((void**)&off,  g_off);
    cudaGetSymbolAddress((void**)&cur,  g_cur);
    cudaGetSymbolAddress((void**)&bsum, g_bsum);
    cudaGetSymbolAddress((void**)&eidx, g_eidx);

    float* out   = (float*)d_out;
    float* x_out = out;
    float* c_out = out + (size_t)nx * 64;
    float* r_out = out + (size_t)nx * 64 + (size_t)nc * 64;

    const int gx = (nx + 127) / 128;
    const int gc = (nc + 127) / 128;
    const int gr = (nr + 127) / 128;
    const int nb = (nx + 1023) / 1024;

    cudaFuncSetAttribute((const void*)hmma_gemm<64, true>,
                         cudaFuncAttributeMaxDynamicSharedMemorySize, SMEM_HM);
    cudaFuncSetAttribute((const void*)hmma_gemm<64, false>,
                         cudaFuncAttributeMaxDynamicSharedMemorySize, SMEM_HM);
    cudaFuncSetAttribute((const void*)hmma_gemm<32, true>,
                         cudaFuncAttributeMaxDynamicSharedMemorySize, SMEM_HM);

    // ---- CSR build ----
    zero_kernel<<<(nx + 255) / 256, 256>>>(cur, nx);
    hist_kernel<<<(Etot + 255) / 256, 256>>>(e_xx_d, e_cx_d, e_rx_d, Exx, Ecx, Erx, cur);
    scan1_kernel<<<nb, 1024>>>(cur, off, bsum, nx);
    scan2_kernel<<<1, 32>>>(bsum, nb, off, nx, Etot);
    scan3_kernel<<<nb, 1024>>>(off, bsum, cur, nx);
    fill_kernel<<<(Etot + 255) / 256, 256>>>(e_xx_s, e_xx_d, e_cx_s, e_cx_d,
                                             e_rx_s, e_rx_d, Exx, Ecx, Erx, cur, eidx);

    // ---- per-node transforms (tensor cores, bf16x2 split) ----
    hmma_gemm<64, true ><<<gx, 256, SMEM_HM>>>(x, nx, W_x,  b_x,  agg);
    hmma_gemm<64, true ><<<gx, 256, SMEM_HM>>>(x, nx, W_xx, b_xx, txx);
    hmma_gemm<32, true ><<<gc, 256, SMEM_HM>>>(c, nc, W_cx, b_cx, tcx);
    hmma_gemm<32, true ><<<gc, 256, SMEM_HM>>>(c, nc, W_c,  b_c,  c_out);
    gemm_small<48, true ><<<gr, 128>>>(r, nr, W_rx, b_rx, trx);
    gemm_small<48, true ><<<gr, 128>>>(r, nr, W_r,  b_r,  r_out);

    // ---- aggregate (no atomics) ----
    gather_accum<<<(nx + 7) / 8, 256>>>(txx, tcx, trx, agg, off, eidx, nx);

    // ---- output projection ----
    hmma_gemm<64, false><<<gx, 256, SMEM_HM>>>(agg, nx, W_pool, b_pool, x_out);
}